// round 1
// baseline (speedup 1.0000x reference)
#include <cuda_runtime.h>
#include <cstdint>
#include <cfloat>

// Problem constants (fixed shapes from the reference)
#define BATCH 16
#define NPTS  100000
#define NCLS  30
#define NBINS 256
#define CAP   4096          // max candidates collected per (b,c)
#define TOPK  200           // PRE_NMS_TOPK
#define MAXDET 100
#define POOL  (NCLS * TOPK) // 6000 per image
#define POOL_P 8192         // next pow2 for bitonic
#define ELEMS_PER_IMG (NPTS * NCLS)   // 3,000,000
#define CHUNKS 60
#define CHUNK_SZ (ELEMS_PER_IMG / CHUNKS) // 50,000

// -------- device scratch (no allocations allowed) --------
__device__ int   g_hist[BATCH * NCLS * NBINS];
__device__ int   g_cnt [BATCH * NCLS];
__device__ int   g_hi  [BATCH * NCLS];
__device__ float g_candS[BATCH * NCLS * CAP];
__device__ int   g_candI[BATCH * NCLS * CAP];
__device__ float g_kscore[BATCH * NCLS * TOPK];
__device__ int   g_kidx  [BATCH * NCLS * TOPK];

// monotone float<->uint transform (handles -inf correctly)
__device__ __forceinline__ unsigned orderable(float f) {
    unsigned u = __float_as_uint(f);
    return u ^ (((int)u >> 31) ? 0xFFFFFFFFu : 0x80000000u);
}
__device__ __forceinline__ float from_orderable(unsigned o) {
    unsigned bits = (o & 0x80000000u) ? (o ^ 0x80000000u) : ~o;
    return __uint_as_float(bits);
}

// -------- kernel 0: zero scratch counters --------
__global__ void kzero() {
    int i = blockIdx.x * blockDim.x + threadIdx.x;
    if (i < BATCH * NCLS * NBINS) g_hist[i] = 0;
    if (i < BATCH * NCLS)         g_cnt[i]  = 0;
}

// -------- kernel 1: per-(b,c) score histogram (coalesced scan) --------
__global__ void khist(const float* __restrict__ cls) {
    __shared__ int sh[NCLS * NBINS];
    for (int i = threadIdx.x; i < NCLS * NBINS; i += blockDim.x) sh[i] = 0;
    __syncthreads();

    const int b = blockIdx.y;
    const float* p = cls + (long long)b * ELEMS_PER_IMG;
    const int start = blockIdx.x * CHUNK_SZ;
    const int end = start + CHUNK_SZ;
    for (int i = start + threadIdx.x; i < end; i += blockDim.x) {
        float v = p[i];
        if (v > 0.01f) {
            int c = i % NCLS;
            int bin = min((int)(v * 256.0f), NBINS - 1);
            atomicAdd(&sh[c * NBINS + bin], 1);
        }
    }
    __syncthreads();
    int base = b * NCLS * NBINS;
    for (int i = threadIdx.x; i < NCLS * NBINS; i += blockDim.x) {
        int v = sh[i];
        if (v) atomicAdd(&g_hist[base + i], v);
    }
}

// -------- kernel 2: find cutoff bin (cumulative-from-top >= TOPK) --------
__global__ void kcut() {
    int t = blockIdx.x * blockDim.x + threadIdx.x;
    if (t >= BATCH * NCLS) return;
    const int* h = &g_hist[t * NBINS];
    int cum = 0, hi = 0;
    for (int bin = NBINS - 1; bin >= 0; --bin) {
        cum += h[bin];
        if (cum >= TOPK) { hi = bin; break; }
    }
    g_hi[t] = hi;
}

// -------- kernel 3: collect candidates >= cutoff (coalesced scan) --------
__global__ void kcollect(const float* __restrict__ cls) {
    __shared__ int shHi[NCLS];
    const int b = blockIdx.y;
    for (int i = threadIdx.x; i < NCLS; i += blockDim.x) shHi[i] = g_hi[b * NCLS + i];
    __syncthreads();

    const float* p = cls + (long long)b * ELEMS_PER_IMG;
    const int start = blockIdx.x * CHUNK_SZ;
    const int end = start + CHUNK_SZ;
    for (int i = start + threadIdx.x; i < end; i += blockDim.x) {
        float v = p[i];
        if (v > 0.01f) {
            int c = i % NCLS;
            int bin = min((int)(v * 256.0f), NBINS - 1);
            if (bin >= shHi[c]) {
                int bc = b * NCLS + c;
                int slot = atomicAdd(&g_cnt[bc], 1);
                if (slot < CAP) {
                    g_candS[bc * CAP + slot] = v;
                    g_candI[bc * CAP + slot] = i / NCLS;
                }
            }
        }
    }
}

// -------- kernel 4: per-(b,c) exact top-200 (bitonic) + sequential NMS --------
__global__ void ksortnms(const float* __restrict__ boxes) {
    const int bc = blockIdx.x;
    const int b = bc / NCLS;

    __shared__ unsigned long long keys[CAP];
    __shared__ float sx1[TOPK], sy1[TOPK], sx2[TOPK], sy2[TOPK], sarea[TOPK], sscore[TOPK];
    __shared__ int sidx[TOPK], skeep[TOPK];
    __shared__ int shK, shP;

    if (threadIdx.x == 0) {
        int K = g_cnt[bc];
        if (K > CAP) K = CAP;
        int P = 256;
        while (P < K) P <<= 1;
        shK = K; shP = P;
    }
    __syncthreads();
    const int K = shK, P = shP;

    for (int i = threadIdx.x; i < P; i += blockDim.x) {
        if (i < K) {
            unsigned inv = ~orderable(g_candS[bc * CAP + i]);
            keys[i] = ((unsigned long long)inv << 32) | (unsigned)g_candI[bc * CAP + i];
        } else {
            keys[i] = 0xFFFFFFFFFFFFFFFFull;
        }
    }
    __syncthreads();

    // bitonic sort ascending: (desc score, asc index) == jax top_k order
    for (int k = 2; k <= P; k <<= 1) {
        for (int j = k >> 1; j > 0; j >>= 1) {
            for (int i = threadIdx.x; i < P; i += blockDim.x) {
                int ixj = i ^ j;
                if (ixj > i) {
                    bool up = ((i & k) == 0);
                    unsigned long long a = keys[i], bb = keys[ixj];
                    if ((a > bb) == up) { keys[i] = bb; keys[ixj] = a; }
                }
            }
            __syncthreads();
        }
    }

    const int M = min(K, TOPK);
    if ((int)threadIdx.x < M) {
        int j = threadIdx.x;
        unsigned long long key = keys[j];
        unsigned inv = (unsigned)(key >> 32);
        float s = from_orderable(~inv);
        int n = (int)(key & 0xFFFFFFFFu);
        sscore[j] = s;
        sidx[j] = n;
        const float4 bx = *(const float4*)(boxes + ((long long)b * NPTS + n) * 4);
        sx1[j] = bx.x; sy1[j] = bx.y; sx2[j] = bx.z; sy2[j] = bx.w;
        sarea[j] = fmaxf(bx.z - bx.x, 0.f) * fmaxf(bx.w - bx.y, 0.f);
        skeep[j] = 1;
    }
    __syncthreads();

    // sequential greedy NMS, exactly like the reference fori_loop
    for (int i = 0; i < M; i++) {
        if (skeep[i]) {
            int j = threadIdx.x;
            if (j > i && j < M && skeep[j]) {
                float xx1 = fmaxf(sx1[i], sx1[j]);
                float yy1 = fmaxf(sy1[i], sy1[j]);
                float xx2 = fminf(sx2[i], sx2[j]);
                float yy2 = fminf(sy2[i], sy2[j]);
                float inter = fmaxf(xx2 - xx1, 0.f) * fmaxf(yy2 - yy1, 0.f);
                float uni = sarea[i] + sarea[j] - inter;
                float iou = inter / fmaxf(uni, 1e-8f);
                if (iou > 0.5f) skeep[j] = 0;
            }
        }
        __syncthreads();
    }

    const float NEGINF = __int_as_float(0xFF800000);
    for (int j = threadIdx.x; j < TOPK; j += blockDim.x) {
        bool live = (j < M) && skeep[j];
        g_kscore[bc * TOPK + j] = live ? sscore[j] : NEGINF;
        g_kidx  [bc * TOPK + j] = (j < M) ? sidx[j] : 0;
    }
}

// -------- kernel 5: per-image top-100 over 6000 + gather outputs --------
__global__ void kfinal(const float* __restrict__ boxes,
                       const float* __restrict__ rot,
                       const float* __restrict__ tr,
                       float* __restrict__ out) {
    extern __shared__ unsigned long long fk[];
    const int b = blockIdx.x;

    for (int e = threadIdx.x; e < POOL_P; e += blockDim.x) {
        if (e < POOL) {
            float s = g_kscore[b * POOL + e];
            unsigned inv = ~orderable(s);
            fk[e] = ((unsigned long long)inv << 32) | (unsigned)e; // flat idx = c*200+j
        } else {
            fk[e] = 0xFFFFFFFFFFFFFFFFull;
        }
    }
    __syncthreads();

    for (int k = 2; k <= POOL_P; k <<= 1) {
        for (int j = k >> 1; j > 0; j >>= 1) {
            for (int i = threadIdx.x; i < POOL_P; i += blockDim.x) {
                int ixj = i ^ j;
                if (ixj > i) {
                    bool up = ((i & k) == 0);
                    unsigned long long a = fk[i], bb = fk[ixj];
                    if ((a > bb) == up) { fk[i] = bb; fk[ixj] = a; }
                }
            }
            __syncthreads();
        }
    }

    if ((int)threadIdx.x < MAXDET) {
        int j = threadIdx.x;
        unsigned long long key = fk[j];
        unsigned inv = (unsigned)(key >> 32);
        float s = from_orderable(~inv);
        int e = (int)(key & 0xFFFFFFFFu);
        int c = e / TOPK;
        int n = g_kidx[b * POOL + e];
        bool valid = !isinf(s);

        float* ob = out;                                  // [B,100,4]
        float* os = out + BATCH * MAXDET * 4;             // [B,100]
        float* ol = os  + BATCH * MAXDET;                 // [B,100]
        float* orr = ol + BATCH * MAXDET;                 // [B,100,3]
        float* ot = orr + BATCH * MAXDET * 3;             // [B,100,3]

        const float4 bx = *(const float4*)(boxes + ((long long)b * NPTS + n) * 4);
        int o4 = (b * MAXDET + j) * 4;
        ob[o4 + 0] = valid ? bx.x : -1.f;
        ob[o4 + 1] = valid ? bx.y : -1.f;
        ob[o4 + 2] = valid ? bx.z : -1.f;
        ob[o4 + 3] = valid ? bx.w : -1.f;

        os[b * MAXDET + j] = valid ? s : -1.f;
        ol[b * MAXDET + j] = valid ? (float)c : -1.f;

        long long g3 = ((long long)b * NPTS + n) * 3;
        int o3 = (b * MAXDET + j) * 3;
        #pragma unroll
        for (int k2 = 0; k2 < 3; k2++) {
            orr[o3 + k2] = valid ? rot[g3 + k2] : -1.f;
            ot [o3 + k2] = valid ? tr [g3 + k2] : -1.f;
        }
    }
}

extern "C" void kernel_launch(void* const* d_in, const int* in_sizes, int n_in,
                              void* d_out, int out_size) {
    const float* boxes = (const float*)d_in[0];
    const float* cls   = (const float*)d_in[1];
    const float* rot   = (const float*)d_in[2];
    const float* tr    = (const float*)d_in[3];
    float* out = (float*)d_out;

    cudaFuncSetAttribute(kfinal, cudaFuncAttributeMaxDynamicSharedMemorySize,
                         POOL_P * sizeof(unsigned long long));

    kzero<<<(BATCH * NCLS * NBINS + 255) / 256, 256>>>();

    dim3 gscan(CHUNKS, BATCH);
    khist<<<gscan, 256>>>(cls);
    kcut<<<(BATCH * NCLS + 255) / 256, 256>>>();
    kcollect<<<gscan, 256>>>(cls);
    ksortnms<<<BATCH * NCLS, 256>>>(boxes);
    kfinal<<<BATCH, 1024, POOL_P * sizeof(unsigned long long)>>>(boxes, rot, tr, out);
}

// round 3
// speedup vs baseline: 1.0746x; 1.0746x over previous
#include <cuda_runtime.h>
#include <cstdint>
#include <cfloat>

#define BATCH 16
#define NPTS  100000
#define NCLS  30
#define TOPK  200            // PRE_NMS_TOPK
#define MAXDET 100
#define CAP   4096           // per-(b,c) candidate capacity (also sort width)
#define THRESH 0.985f
#define ELEMS_PER_IMG (NPTS * NCLS)     // 3,000,000
#define TOT4  (BATCH * ELEMS_PER_IMG / 4)   // 12,000,000
#define POOL  (NCLS * MAXDET)           // 3000
#define POOL_P 4096
#define PADKEY 0xFFFFFFFFFFFFFFFFull

// -------- device scratch --------
__device__ int   g_cnt [BATCH * NCLS];
__device__ float g_candS[BATCH * NCLS * CAP];
__device__ int   g_candI[BATCH * NCLS * CAP];
__device__ unsigned g_ksc[BATCH * NCLS * MAXDET]; // ~orderable(score) of survivors
__device__ int      g_kn [BATCH * NCLS * MAXDET]; // original point index
__device__ int      g_kcnt[BATCH * NCLS];         // survivors kept (<=100)

__device__ __forceinline__ unsigned orderable(float f) {
    unsigned u = __float_as_uint(f);
    return u ^ (((int)u >> 31) ? 0xFFFFFFFFu : 0x80000000u);
}
__device__ __forceinline__ float from_orderable(unsigned o) {
    unsigned bits = (o & 0x80000000u) ? (o ^ 0x80000000u) : ~o;
    return __uint_as_float(bits);
}

// ascending bitonic sort of keys[0..P), P power of 2, whole block participates
__device__ __forceinline__ void bitonic_sort(unsigned long long* keys, int P) {
    for (int k = 2; k <= P; k <<= 1) {
        for (int j = k >> 1; j > 0; j >>= 1) {
            for (int i = threadIdx.x; i < P; i += blockDim.x) {
                int ixj = i ^ j;
                if (ixj > i) {
                    bool up = ((i & k) == 0);
                    unsigned long long a = keys[i], b = keys[ixj];
                    if ((a > b) == up) { keys[i] = b; keys[ixj] = a; }
                }
            }
            __syncthreads();
        }
    }
}

// -------- kernel 0: zero counters --------
__global__ void kzero() {
    int i = blockIdx.x * blockDim.x + threadIdx.x;
    if (i < BATCH * NCLS) g_cnt[i] = 0;
}

// -------- helper: process one float4 group --------
__device__ __forceinline__ void scan_group(float4 v, int base) {
    if (v.x > THRESH || v.y > THRESH || v.z > THRESH || v.w > THRESH) {
        int b = base / ELEMS_PER_IMG;
        int off = base - b * ELEMS_PER_IMG;
        int n = off / NCLS;
        int c = off - n * NCLS;
        float vv[4] = {v.x, v.y, v.z, v.w};
        #pragma unroll
        for (int k = 0; k < 4; k++) {
            if (vv[k] > THRESH) {
                int bc = b * NCLS + c;
                int slot = atomicAdd(&g_cnt[bc], 1);
                if (slot < CAP) {
                    g_candS[bc * CAP + slot] = vv[k];
                    g_candI[bc * CAP + slot] = n;
                }
            }
            c++;
            if (c == NCLS) { c = 0; n++; }
        }
    }
}

// -------- kernel 1: single fused vectorized scan + threshold collection --------
// 2 float4 loads issued back-to-back per iteration for MLP.
__global__ void kscan(const float4* __restrict__ cls4) {
    const int tid = blockIdx.x * blockDim.x + threadIdx.x;
    const int stride = gridDim.x * blockDim.x;
    for (int i = tid; i < TOT4 / 2; i += stride) {
        int i0 = 2 * i, i1 = 2 * i + 1;
        float4 a = __ldg(&cls4[i0]);
        float4 b = __ldg(&cls4[i1]);
        scan_group(a, i0 * 4);
        scan_group(b, i1 * 4);
    }
}

// -------- kernel 2: per-(b,c) exact top-200 + sequential NMS + compaction --------
__global__ void ksortnms(const float* __restrict__ boxes,
                         const float* __restrict__ cls) {
    const int bc = blockIdx.x;
    const int b = bc / NCLS;
    const int c = bc - b * NCLS;

    __shared__ unsigned long long keys[CAP];           // 32 KB
    __shared__ float sx1[TOPK], sy1[TOPK], sx2[TOPK], sy2[TOPK], sarea[TOPK], sscore[TOPK];
    __shared__ int sidx[TOPK], skeep[TOPK];
    __shared__ int scan_a[256];

    const int cnt = g_cnt[bc];
    const bool normal = (cnt >= TOPK && cnt <= CAP);

    if (normal) {
        int P = 256;
        while (P < cnt) P <<= 1;
        for (int i = threadIdx.x; i < P; i += blockDim.x) {
            if (i < cnt) {
                unsigned inv = ~orderable(g_candS[bc * CAP + i]);
                keys[i] = ((unsigned long long)inv << 32) | (unsigned)g_candI[bc * CAP + i];
            } else keys[i] = PADKEY;
        }
        __syncthreads();
        bitonic_sort(keys, P);
    } else {
        // exact streaming fallback (unreachable for this data distribution)
        const int HALF = CAP / 2;
        for (int i = threadIdx.x; i < CAP; i += blockDim.x) keys[i] = PADKEY;
        __syncthreads();
        for (int cs = 0; cs < NPTS; cs += HALF) {
            for (int j = threadIdx.x; j < HALF; j += blockDim.x) {
                int n = cs + j;
                unsigned long long key = PADKEY;
                if (n < NPTS) {
                    float v = cls[((long long)b * NPTS + n) * NCLS + c];
                    if (v > 0.01f)
                        key = ((unsigned long long)(~orderable(v)) << 32) | (unsigned)n;
                }
                keys[HALF + j] = key;
            }
            __syncthreads();
            bitonic_sort(keys, CAP);
        }
    }

    // load top-200 into NMS arrays
    if ((int)threadIdx.x < TOPK) {
        int j = threadIdx.x;
        unsigned long long key = keys[j];
        unsigned hi = (unsigned)(key >> 32);
        bool live = (hi != 0xFFFFFFFFu);
        float s = from_orderable(~hi);
        int n = live ? (int)(key & 0xFFFFFFFFu) : 0;
        sscore[j] = s;
        sidx[j] = n;
        const float4 bx = *(const float4*)(boxes + ((long long)b * NPTS + n) * 4);
        sx1[j] = bx.x; sy1[j] = bx.y; sx2[j] = bx.z; sy2[j] = bx.w;
        sarea[j] = fmaxf(bx.z - bx.x, 0.f) * fmaxf(bx.w - bx.y, 0.f);
        skeep[j] = live ? 1 : 0;
    }
    __syncthreads();

    // sequential greedy NMS (matches reference fori_loop exactly)
    for (int i = 0; i < TOPK; i++) {
        if (skeep[i]) {
            int j = threadIdx.x;
            if (j > i && j < TOPK && skeep[j]) {
                float xx1 = fmaxf(sx1[i], sx1[j]);
                float yy1 = fmaxf(sy1[i], sy1[j]);
                float xx2 = fminf(sx2[i], sx2[j]);
                float yy2 = fminf(sy2[i], sy2[j]);
                float inter = fmaxf(xx2 - xx1, 0.f) * fmaxf(yy2 - yy1, 0.f);
                float uni = sarea[i] + sarea[j] - inter;
                if (inter / fmaxf(uni, 1e-8f) > 0.5f) skeep[j] = 0;
            }
        }
        __syncthreads();
    }

    // order-preserving compaction of survivors (top-100 per class suffice)
    scan_a[threadIdx.x] = ((int)threadIdx.x < TOPK && skeep[threadIdx.x]) ? 1 : 0;
    for (int off = 1; off < 256; off <<= 1) {
        __syncthreads();
        int v = scan_a[threadIdx.x];
        if ((int)threadIdx.x >= off) v += scan_a[threadIdx.x - off];
        __syncthreads();
        scan_a[threadIdx.x] = v;
    }
    __syncthreads();
    if ((int)threadIdx.x < TOPK && skeep[threadIdx.x]) {
        int pos = scan_a[threadIdx.x] - 1;
        if (pos < MAXDET) {
            g_ksc[bc * MAXDET + pos] = ~orderable(sscore[threadIdx.x]);
            g_kn [bc * MAXDET + pos] = sidx[threadIdx.x];
        }
    }
    if (threadIdx.x == 0) g_kcnt[bc] = min(scan_a[255], MAXDET);
}

// -------- kernel 3: per-image top-100 over pooled survivors + gather --------
__global__ void kfinal(const float* __restrict__ boxes,
                       const float* __restrict__ rot,
                       const float* __restrict__ tr,
                       float* __restrict__ out) {
    __shared__ unsigned long long fk[POOL_P];          // 32 KB
    __shared__ int shCnt[NCLS];
    const int b = blockIdx.x;

    for (int i = threadIdx.x; i < NCLS; i += blockDim.x) shCnt[i] = g_kcnt[b * NCLS + i];
    __syncthreads();

    for (int e = threadIdx.x; e < POOL_P; e += blockDim.x) {
        unsigned long long key = PADKEY;
        if (e < POOL) {
            int c = e / MAXDET;
            int slot = e - c * MAXDET;
            if (slot < shCnt[c]) {
                unsigned hi = g_ksc[(b * NCLS + c) * MAXDET + slot];
                key = ((unsigned long long)hi << 32) | (unsigned)e;
            }
        }
        fk[e] = key;
    }
    __syncthreads();
    bitonic_sort(fk, POOL_P);

    if ((int)threadIdx.x < MAXDET) {
        int j = threadIdx.x;
        unsigned long long key = fk[j];
        unsigned hi = (unsigned)(key >> 32);
        bool valid = (hi != 0xFFFFFFFFu);
        float s = from_orderable(~hi);
        int e = (int)(key & 0xFFFFFFFFu);
        int c = valid ? e / MAXDET : 0;
        int slot = valid ? e - c * MAXDET : 0;
        int n = g_kn[(b * NCLS + c) * MAXDET + slot];

        float* ob = out;
        float* os = out + BATCH * MAXDET * 4;
        float* ol = os  + BATCH * MAXDET;
        float* orr = ol + BATCH * MAXDET;
        float* ot = orr + BATCH * MAXDET * 3;

        const float4 bx = *(const float4*)(boxes + ((long long)b * NPTS + n) * 4);
        int o4 = (b * MAXDET + j) * 4;
        ob[o4 + 0] = valid ? bx.x : -1.f;
        ob[o4 + 1] = valid ? bx.y : -1.f;
        ob[o4 + 2] = valid ? bx.z : -1.f;
        ob[o4 + 3] = valid ? bx.w : -1.f;

        os[b * MAXDET + j] = valid ? s : -1.f;
        ol[b * MAXDET + j] = valid ? (float)c : -1.f;

        long long g3 = ((long long)b * NPTS + n) * 3;
        int o3 = (b * MAXDET + j) * 3;
        #pragma unroll
        for (int k2 = 0; k2 < 3; k2++) {
            orr[o3 + k2] = valid ? rot[g3 + k2] : -1.f;
            ot [o3 + k2] = valid ? tr [g3 + k2] : -1.f;
        }
    }
}

extern "C" void kernel_launch(void* const* d_in, const int* in_sizes, int n_in,
                              void* d_out, int out_size) {
    const float* boxes = (const float*)d_in[0];
    const float* cls   = (const float*)d_in[1];
    const float* rot   = (const float*)d_in[2];
    const float* tr    = (const float*)d_in[3];
    float* out = (float*)d_out;

    kzero<<<2, 256>>>();
    kscan<<<2048, 256>>>((const float4*)cls);
    ksortnms<<<BATCH * NCLS, 256>>>(boxes, cls);
    kfinal<<<BATCH, 1024>>>(boxes, rot, tr, out);
}

// round 4
// speedup vs baseline: 2.0716x; 1.9279x over previous
#include <cuda_runtime.h>
#include <cstdint>
#include <cfloat>

#define BATCH 16
#define NPTS  100000
#define NCLS  30
#define TOPK  200
#define MAXDET 100
#define CAP   1024
#define THRESH 0.9955f
#define ELEMS_PER_IMG (NPTS * NCLS)       // 3,000,000
#define TOT4  (BATCH * ELEMS_PER_IMG / 4) // 12,000,000
#define F4_PER_IMG (ELEMS_PER_IMG / 4)    // 750,000
#define NBC   (BATCH * NCLS)
#define PADKEY 0xFFFFFFFFFFFFFFFFull
#define MASKW 7                            // ceil(200/32)

// -------- device scratch --------
__device__ int      g_cnt [NBC];
__device__ float    g_candS[NBC * CAP];
__device__ int      g_candI[NBC * CAP];
__device__ unsigned g_khi[NBC * MAXDET];   // ~orderable(score), survivors, desc order
__device__ int      g_kn [NBC * MAXDET];   // point index n
__device__ int      g_kj [NBC * MAXDET];   // original rank j in top-200 (for flat idx)
__device__ int      g_kcnt[NBC];

__device__ __forceinline__ unsigned orderable(float f) {
    unsigned u = __float_as_uint(f);
    return u ^ (((int)u >> 31) ? 0xFFFFFFFFu : 0x80000000u);
}
__device__ __forceinline__ float from_orderable(unsigned o) {
    unsigned bits = (o & 0x80000000u) ? (o ^ 0x80000000u) : ~o;
    return __uint_as_float(bits);
}

__device__ __forceinline__ void bitonic_sort(unsigned long long* keys, int P) {
    for (int k = 2; k <= P; k <<= 1) {
        for (int j = k >> 1; j > 0; j >>= 1) {
            for (int i = threadIdx.x; i < P; i += blockDim.x) {
                int ixj = i ^ j;
                if (ixj > i) {
                    bool up = ((i & k) == 0);
                    unsigned long long a = keys[i], b = keys[ixj];
                    if ((a > b) == up) { keys[i] = b; keys[ixj] = a; }
                }
            }
            __syncthreads();
        }
    }
}

// -------- kernel 0 --------
__global__ void kzero() {
    int i = blockIdx.x * blockDim.x + threadIdx.x;
    if (i < NBC) g_cnt[i] = 0;
}

// -------- kernel 1: fused coalesced scan + threshold collect --------
__device__ __forceinline__ void scan_group(float4 v, int i4) {
    if (v.x > THRESH || v.y > THRESH || v.z > THRESH || v.w > THRESH) {
        int b = i4 / F4_PER_IMG;
        int base = i4 * 4 - b * ELEMS_PER_IMG;      // element offset within image
        int n = base / NCLS;
        int c = base - n * NCLS;
        float vv[4] = {v.x, v.y, v.z, v.w};
        #pragma unroll
        for (int k = 0; k < 4; k++) {
            if (vv[k] > THRESH) {
                int bc = b * NCLS + c;
                int slot = atomicAdd(&g_cnt[bc], 1);
                if (slot < CAP) {
                    g_candS[bc * CAP + slot] = vv[k];
                    g_candI[bc * CAP + slot] = n;
                }
            }
            c++;
            if (c == NCLS) { c = 0; n++; }
        }
    }
}

__global__ void kscan(const float4* __restrict__ cls4) {
    const int tid = blockIdx.x * blockDim.x + threadIdx.x;
    const int stride = gridDim.x * blockDim.x;
    for (int i = tid; i < TOT4; i += 2 * stride) {
        float4 a = __ldg(&cls4[i]);
        int i2 = i + stride;
        if (i2 < TOT4) {
            float4 b = __ldg(&cls4[i2]);   // second coalesced stream -> MLP=2
            scan_group(a, i);
            scan_group(b, i2);
        } else {
            scan_group(a, i);
        }
    }
}

// -------- kernel 2: exact top-200 + mask-based NMS + compaction --------
__global__ void ksortnms(const float* __restrict__ boxes,
                         const float* __restrict__ cls) {
    const int bc = blockIdx.x;
    const int b = bc / NCLS;
    const int c = bc - b * NCLS;
    const int tid = threadIdx.x;

    __shared__ unsigned long long keys[CAP];                       // 8 KB
    __shared__ float sx1[TOPK], sy1[TOPK], sx2[TOPK], sy2[TOPK], sarea[TOPK], sscore[TOPK];
    __shared__ int sidx[TOPK], slive[TOPK];
    __shared__ unsigned smask[TOPK * MASKW];                       // 5.6 KB
    __shared__ unsigned skeepw[MASKW];

    const int cnt = g_cnt[bc];
    const bool normal = (cnt >= TOPK && cnt <= CAP);

    if (normal) {
        int P = 256;
        while (P < cnt) P <<= 1;
        for (int i = tid; i < P; i += blockDim.x) {
            if (i < cnt) {
                unsigned inv = ~orderable(g_candS[bc * CAP + i]);
                keys[i] = ((unsigned long long)inv << 32) | (unsigned)g_candI[bc * CAP + i];
            } else keys[i] = PADKEY;
        }
        __syncthreads();
        bitonic_sort(keys, P);
    } else {
        // exact streaming fallback (unreachable for this data distribution)
        const int HALF = CAP / 2;
        for (int i = tid; i < CAP; i += blockDim.x) keys[i] = PADKEY;
        __syncthreads();
        for (int cs = 0; cs < NPTS; cs += HALF) {
            for (int j = tid; j < HALF; j += blockDim.x) {
                int n = cs + j;
                unsigned long long key = PADKEY;
                if (n < NPTS) {
                    float v = cls[((long long)b * NPTS + n) * NCLS + c];
                    if (v > 0.01f)
                        key = ((unsigned long long)(~orderable(v)) << 32) | (unsigned)n;
                }
                keys[HALF + j] = key;
            }
            __syncthreads();
            bitonic_sort(keys, CAP);
        }
    }

    // load top-200
    if (tid < TOPK) {
        int j = tid;
        unsigned long long key = keys[j];
        unsigned hi = (unsigned)(key >> 32);
        bool live = (hi != 0xFFFFFFFFu);
        int n = live ? (int)(key & 0xFFFFFFFFu) : 0;
        sscore[j] = from_orderable(~hi);
        sidx[j] = n;
        const float4 bx = *(const float4*)(boxes + ((long long)b * NPTS + n) * 4);
        sx1[j] = bx.x; sy1[j] = bx.y; sx2[j] = bx.z; sy2[j] = bx.w;
        sarea[j] = fmaxf(bx.z - bx.x, 0.f) * fmaxf(bx.w - bx.y, 0.f);
        slive[j] = live ? 1 : 0;
    }
    __syncthreads();

    // build 200 x 224-bit suppression masks in parallel (j > i only)
    for (int cell = tid; cell < TOPK * MASKW; cell += blockDim.x) {
        int i = cell / MASKW, w = cell - i * MASKW;
        unsigned m = 0;
        int j0 = w * 32;
        if (j0 + 31 > i) {
            float x1i = sx1[i], y1i = sy1[i], x2i = sx2[i], y2i = sy2[i], ai = sarea[i];
            #pragma unroll 8
            for (int bit = 0; bit < 32; bit++) {
                int j = j0 + bit;
                if (j > i && j < TOPK) {
                    float xx1 = fmaxf(x1i, sx1[j]);
                    float yy1 = fmaxf(y1i, sy1[j]);
                    float xx2 = fminf(x2i, sx2[j]);
                    float yy2 = fminf(y2i, sy2[j]);
                    float inter = fmaxf(xx2 - xx1, 0.f) * fmaxf(yy2 - yy1, 0.f);
                    float uni = ai + sarea[j] - inter;
                    if (inter / fmaxf(uni, 1e-8f) > 0.5f) m |= 1u << bit;
                }
            }
        }
        smask[cell] = m;
    }
    __syncthreads();

    // sequential greedy resolve on warp 0 (lane w owns bits [32w,32w+32))
    if (tid < 32) {
        const unsigned FULL = 0xFFFFFFFFu;
        int lane = tid;
        unsigned keepw = 0;
        if (lane < MASKW) {
            for (int bit = 0; bit < 32; bit++) {
                int j = lane * 32 + bit;
                if (j < TOPK && slive[j]) keepw |= 1u << bit;
            }
        }
        for (int i = 0; i < TOPK; i++) {
            unsigned ow = __shfl_sync(FULL, keepw, i >> 5);
            if ((ow >> (i & 31)) & 1u) {
                unsigned mm = (lane < MASKW) ? smask[i * MASKW + lane] : 0u;
                keepw &= ~mm;
            }
        }
        // order-preserving compaction, keep first 100 survivors
        int pc = (lane < MASKW) ? __popc(keepw) : 0;
        int incl = pc;
        #pragma unroll
        for (int off = 1; off < 32; off <<= 1) {
            int v = __shfl_up_sync(FULL, incl, off);
            if (lane >= off) incl += v;
        }
        int excl = incl - pc;
        int total = __shfl_sync(FULL, incl, 31);
        if (lane < MASKW) {
            unsigned wb = keepw;
            int r = excl;
            while (wb) {
                int bit = __ffs(wb) - 1; wb &= wb - 1;
                int j = lane * 32 + bit;
                if (r < MAXDET) {
                    g_khi[bc * MAXDET + r] = ~orderable(sscore[j]);
                    g_kn [bc * MAXDET + r] = sidx[j];
                    g_kj [bc * MAXDET + r] = j;
                }
                r++;
            }
        }
        if (lane == 0) g_kcnt[bc] = min(total, MAXDET);
    }
}

// -------- kernel 3: per-image exact top-100 via rank selection --------
__global__ void kfinal(const float* __restrict__ boxes,
                       const float* __restrict__ rot,
                       const float* __restrict__ tr,
                       float* __restrict__ out) {
    __shared__ unsigned long long keys[4096];   // 32 KB (also fallback sort buffer)
    __shared__ int narr[NCLS * MAXDET];         // 12 KB
    __shared__ unsigned long long coll[256];    // 2 KB
    __shared__ int cnts[NCLS], pref[NCLS + 1];
    __shared__ int sT, sCnt, sC, sMn, sMx;

    const int b = blockIdx.x;
    const int tid = threadIdx.x;

    if (tid < NCLS) cnts[tid] = g_kcnt[b * NCLS + tid];
    __syncthreads();
    if (tid == 0) {
        int acc = 0;
        for (int c = 0; c < NCLS; c++) { pref[c] = acc; acc += cnts[c]; }
        pref[NCLS] = acc; sT = acc;
        sMn = 0x7FFFFFFF; sMx = 0; // as signed compares on unsigned<2^31? use atomicMin on int after shift
    }
    __syncthreads();
    const int T = sT;

    // compact load:  key = hi<<32 | flat<<12 | pos
    for (int e = tid; e < NCLS * MAXDET; e += blockDim.x) {
        int c = e / MAXDET, s = e - c * MAXDET;
        if (s < cnts[c]) {
            int pos = pref[c] + s;
            int gi = (b * NCLS + c) * MAXDET + s;
            unsigned hi = g_khi[gi];
            int j = g_kj[gi];
            unsigned flat = (unsigned)(c * TOPK + j);
            keys[pos] = ((unsigned long long)hi << 32) | (flat << 12) | (unsigned)pos;
            narr[pos] = g_kn[gi];
        }
    }
    // min/max of hi (hi has top bit set for positive scores -> shift right 1 for int atomics)
    __syncthreads();
    {
        int lmn = 0x7FFFFFFF, lmx = 0;
        for (int e = tid; e < T; e += blockDim.x) {
            int h = (int)((unsigned)(keys[e] >> 32) >> 1);
            lmn = min(lmn, h); lmx = max(lmx, h);
        }
        atomicMin(&sMn, lmn); atomicMax(&sMx, lmx);
    }
    __syncthreads();

    const int target = min(T, MAXDET);
    unsigned X = 0xFFFFFFFFu;
    if (T > 0) {
        unsigned lo = ((unsigned)sMn) << 1, hi_ = (((unsigned)sMx) << 1) | 1u;
        while (lo < hi_) {
            unsigned mid = lo + ((hi_ - lo) >> 1);
            __syncthreads();
            if (tid == 0) sCnt = 0;
            __syncthreads();
            int lc = 0;
            for (int e = tid; e < T; e += blockDim.x)
                lc += ((unsigned)(keys[e] >> 32) <= mid);
            // warp reduce then one atomic per warp
            for (int off = 16; off; off >>= 1) lc += __shfl_down_sync(0xFFFFFFFFu, lc, off);
            if ((tid & 31) == 0 && lc) atomicAdd(&sCnt, lc);
            __syncthreads();
            if (sCnt >= target) hi_ = mid; else lo = mid + 1;
        }
        X = lo;
    }

    // collect keys with hi <= X
    __syncthreads();
    if (tid == 0) sC = 0;
    for (int e = tid; e < 256; e += blockDim.x) coll[e] = PADKEY;
    __syncthreads();
    for (int e = tid; e < T; e += blockDim.x) {
        if ((unsigned)(keys[e] >> 32) <= X) {
            int slot = atomicAdd(&sC, 1);
            if (slot < 256) coll[slot] = keys[e];
        }
    }
    __syncthreads();
    const int C = sC;
    unsigned long long* res;
    if (C <= 256) {
        bitonic_sort(coll, 256);
        res = coll;
    } else {
        // pathological mass-tie fallback: full sort of all survivors
        int P = 256; while (P < T) P <<= 1;
        for (int e = tid; e < P; e += blockDim.x)
            if (e >= T) keys[e] = PADKEY;
        __syncthreads();
        bitonic_sort(keys, P);
        res = keys;
    }

    if (tid < MAXDET) {
        int j = tid;
        unsigned long long key = res[j];
        unsigned hi = (unsigned)(key >> 32);
        bool valid = (key != PADKEY) && (hi != 0xFFFFFFFFu);
        float s = from_orderable(~hi);
        unsigned low = (unsigned)key;
        int pos = (int)(low & 0xFFFu);
        int flat = (int)(low >> 12);
        int c = valid ? flat / TOPK : 0;
        int n = valid ? narr[pos] : 0;

        float* ob = out;
        float* os = out + BATCH * MAXDET * 4;
        float* ol = os  + BATCH * MAXDET;
        float* orr = ol + BATCH * MAXDET;
        float* ot = orr + BATCH * MAXDET * 3;

        const float4 bx = *(const float4*)(boxes + ((long long)b * NPTS + n) * 4);
        int o4 = (b * MAXDET + j) * 4;
        ob[o4 + 0] = valid ? bx.x : -1.f;
        ob[o4 + 1] = valid ? bx.y : -1.f;
        ob[o4 + 2] = valid ? bx.z : -1.f;
        ob[o4 + 3] = valid ? bx.w : -1.f;

        os[b * MAXDET + j] = valid ? s : -1.f;
        ol[b * MAXDET + j] = valid ? (float)c : -1.f;

        long long g3 = ((long long)b * NPTS + n) * 3;
        int o3 = (b * MAXDET + j) * 3;
        #pragma unroll
        for (int k2 = 0; k2 < 3; k2++) {
            orr[o3 + k2] = valid ? rot[g3 + k2] : -1.f;
            ot [o3 + k2] = valid ? tr [g3 + k2] : -1.f;
        }
    }
}

extern "C" void kernel_launch(void* const* d_in, const int* in_sizes, int n_in,
                              void* d_out, int out_size) {
    const float* boxes = (const float*)d_in[0];
    const float* cls   = (const float*)d_in[1];
    const float* rot   = (const float*)d_in[2];
    const float* tr    = (const float*)d_in[3];
    float* out = (float*)d_out;

    kzero<<<2, 256>>>();
    kscan<<<2048, 256>>>((const float4*)cls);
    ksortnms<<<NBC, 256>>>(boxes, cls);
    kfinal<<<BATCH, 256>>>(boxes, rot, tr, out);
}

// round 5
// speedup vs baseline: 2.3677x; 1.1429x over previous
#include <cuda_runtime.h>
#include <cstdint>
#include <cfloat>

#define BATCH 16
#define NPTS  100000
#define NCLS  30
#define TOPK  200
#define MAXDET 100
#define CAP   1024
#define THRESH 0.9955f
#define ELEMS_PER_IMG (NPTS * NCLS)       // 3,000,000
#define TOT4  (BATCH * ELEMS_PER_IMG / 4) // 12,000,000
#define NBC   (BATCH * NCLS)
#define PADKEY 0xFFFFFFFFFFFFFFFFull
#define MASKW 7                            // ceil(200/32)
#define SCAP  2048                         // per-block staging capacity
#define NHBIN 2048

// -------- device scratch --------
__device__ int      g_cnt [NBC];           // zero-init at load; re-zeroed by kfinal tail
__device__ float    g_candS[NBC * CAP];
__device__ int      g_candI[NBC * CAP];
__device__ unsigned g_khi[NBC * MAXDET];   // ~orderable(score), survivors, desc score order
__device__ int      g_kn [NBC * MAXDET];   // point index n
__device__ int      g_kcnt[NBC];

__device__ __forceinline__ unsigned orderable(float f) {
    unsigned u = __float_as_uint(f);
    return u ^ (((int)u >> 31) ? 0xFFFFFFFFu : 0x80000000u);
}
__device__ __forceinline__ float from_orderable(unsigned o) {
    unsigned bits = (o & 0x80000000u) ? (o ^ 0x80000000u) : ~o;
    return __uint_as_float(bits);
}

__device__ __forceinline__ void bitonic_sort(unsigned long long* keys, int P) {
    for (int k = 2; k <= P; k <<= 1) {
        for (int j = k >> 1; j > 0; j >>= 1) {
            for (int i = threadIdx.x; i < P; i += blockDim.x) {
                int ixj = i ^ j;
                if (ixj > i) {
                    bool up = ((i & k) == 0);
                    unsigned long long a = keys[i], b = keys[ixj];
                    if ((a > b) == up) { keys[i] = b; keys[ixj] = a; }
                }
            }
            __syncthreads();
        }
    }
}

// ================= kernel 1: scan with smem hit-staging =================
__global__ void kscan(const float4* __restrict__ cls4) {
    __shared__ int sCnt;
    __shared__ float sVal[SCAP];
    __shared__ int   sIdx[SCAP];   // global element index (< 48M, fits int)

    if (threadIdx.x == 0) sCnt = 0;
    __syncthreads();

    const int S = gridDim.x * blockDim.x;
    const int tid = blockIdx.x * blockDim.x + threadIdx.x;

    for (int i = tid; i < TOT4; i += 4 * S) {
        #pragma unroll
        for (int st = 0; st < 4; st++) {
            int idx = i + st * S;
            if (idx < TOT4) {
                float4 v = __ldg(&cls4[idx]);
                if (v.x > THRESH || v.y > THRESH || v.z > THRESH || v.w > THRESH) {
                    float vv[4] = {v.x, v.y, v.z, v.w};
                    #pragma unroll
                    for (int k = 0; k < 4; k++) {
                        if (vv[k] > THRESH) {
                            int slot = atomicAdd(&sCnt, 1);
                            if (slot < SCAP) {
                                sVal[slot] = vv[k];
                                sIdx[slot] = idx * 4 + k;
                            } else {
                                // staging overflow (statistically unreachable): direct path
                                int gidx = idx * 4 + k;
                                int b = gidx / ELEMS_PER_IMG;
                                int off = gidx - b * ELEMS_PER_IMG;
                                int n = off / NCLS;
                                int c = off - n * NCLS;
                                int bc = b * NCLS + c;
                                int gs = atomicAdd(&g_cnt[bc], 1);
                                if (gs < CAP) {
                                    g_candS[bc * CAP + gs] = vv[k];
                                    g_candI[bc * CAP + gs] = n;
                                }
                            }
                        }
                    }
                }
            }
        }
    }
    __syncthreads();

    const int m = min(sCnt, SCAP);
    for (int e = threadIdx.x; e < m; e += blockDim.x) {
        int gidx = sIdx[e];
        float v = sVal[e];
        int b = gidx / ELEMS_PER_IMG;
        int off = gidx - b * ELEMS_PER_IMG;
        int n = off / NCLS;
        int c = off - n * NCLS;
        int bc = b * NCLS + c;
        int slot = atomicAdd(&g_cnt[bc], 1);
        if (slot < CAP) {
            g_candS[bc * CAP + slot] = v;
            g_candI[bc * CAP + slot] = n;
        }
    }
}

// ========== kernel 2: exact top-200 + mask NMS + compaction ==========
__global__ void ksortnms(const float* __restrict__ boxes,
                         const float* __restrict__ cls) {
    const int bc = blockIdx.x;
    const int b = bc / NCLS;
    const int c = bc - b * NCLS;
    const int tid = threadIdx.x;

    __shared__ unsigned long long keys[CAP];                       // 8 KB
    __shared__ float sx1[TOPK], sy1[TOPK], sx2[TOPK], sy2[TOPK], sarea[TOPK], sscore[TOPK];
    __shared__ int sidx[TOPK], slive[TOPK];
    __shared__ unsigned smask[TOPK * MASKW];                       // 5.6 KB

    const int cnt = g_cnt[bc];
    const bool normal = (cnt >= TOPK && cnt <= CAP);

    if (normal) {
        int P = 256;
        while (P < cnt) P <<= 1;
        for (int i = tid; i < P; i += blockDim.x) {
            if (i < cnt) {
                unsigned inv = ~orderable(g_candS[bc * CAP + i]);
                keys[i] = ((unsigned long long)inv << 32) | (unsigned)g_candI[bc * CAP + i];
            } else keys[i] = PADKEY;
        }
        __syncthreads();
        bitonic_sort(keys, P);
    } else {
        // exact streaming fallback (unreachable for this data distribution)
        const int HALF = CAP / 2;
        for (int i = tid; i < CAP; i += blockDim.x) keys[i] = PADKEY;
        __syncthreads();
        for (int cs = 0; cs < NPTS; cs += HALF) {
            for (int j = tid; j < HALF; j += blockDim.x) {
                int n = cs + j;
                unsigned long long key = PADKEY;
                if (n < NPTS) {
                    float v = cls[((long long)b * NPTS + n) * NCLS + c];
                    if (v > 0.01f)
                        key = ((unsigned long long)(~orderable(v)) << 32) | (unsigned)n;
                }
                keys[HALF + j] = key;
            }
            __syncthreads();
            bitonic_sort(keys, CAP);
        }
    }

    if (tid < TOPK) {
        int j = tid;
        unsigned long long key = keys[j];
        unsigned hi = (unsigned)(key >> 32);
        bool live = (hi != 0xFFFFFFFFu);
        int n = live ? (int)(key & 0xFFFFFFFFu) : 0;
        sscore[j] = from_orderable(~hi);
        sidx[j] = n;
        const float4 bx = *(const float4*)(boxes + ((long long)b * NPTS + n) * 4);
        sx1[j] = bx.x; sy1[j] = bx.y; sx2[j] = bx.z; sy2[j] = bx.w;
        sarea[j] = fmaxf(bx.z - bx.x, 0.f) * fmaxf(bx.w - bx.y, 0.f);
        slive[j] = live ? 1 : 0;
    }
    __syncthreads();

    for (int cell = tid; cell < TOPK * MASKW; cell += blockDim.x) {
        int i = cell / MASKW, w = cell - i * MASKW;
        unsigned m = 0;
        int j0 = w * 32;
        if (j0 + 31 > i) {
            float x1i = sx1[i], y1i = sy1[i], x2i = sx2[i], y2i = sy2[i], ai = sarea[i];
            #pragma unroll 8
            for (int bit = 0; bit < 32; bit++) {
                int j = j0 + bit;
                if (j > i && j < TOPK) {
                    float xx1 = fmaxf(x1i, sx1[j]);
                    float yy1 = fmaxf(y1i, sy1[j]);
                    float xx2 = fminf(x2i, sx2[j]);
                    float yy2 = fminf(y2i, sy2[j]);
                    float inter = fmaxf(xx2 - xx1, 0.f) * fmaxf(yy2 - yy1, 0.f);
                    float uni = ai + sarea[j] - inter;
                    if (inter / fmaxf(uni, 1e-8f) > 0.5f) m |= 1u << bit;
                }
            }
        }
        smask[cell] = m;
    }
    __syncthreads();

    if (tid < 32) {
        const unsigned FULL = 0xFFFFFFFFu;
        int lane = tid;
        unsigned keepw = 0;
        if (lane < MASKW) {
            for (int bit = 0; bit < 32; bit++) {
                int j = lane * 32 + bit;
                if (j < TOPK && slive[j]) keepw |= 1u << bit;
            }
        }
        for (int i = 0; i < TOPK; i++) {
            unsigned ow = __shfl_sync(FULL, keepw, i >> 5);
            if ((ow >> (i & 31)) & 1u) {
                unsigned mm = (lane < MASKW) ? smask[i * MASKW + lane] : 0u;
                keepw &= ~mm;
            }
        }
        int pc = (lane < MASKW) ? __popc(keepw) : 0;
        int incl = pc;
        #pragma unroll
        for (int off = 1; off < 32; off <<= 1) {
            int v = __shfl_up_sync(FULL, incl, off);
            if (lane >= off) incl += v;
        }
        int excl = incl - pc;
        int total = __shfl_sync(FULL, incl, 31);
        if (lane < MASKW) {
            unsigned wb = keepw;
            int r = excl;
            while (wb) {
                int bit = __ffs(wb) - 1; wb &= wb - 1;
                int j = lane * 32 + bit;
                if (r < MAXDET) {
                    g_khi[bc * MAXDET + r] = ~orderable(sscore[j]);
                    g_kn [bc * MAXDET + r] = sidx[j];
                }
                r++;
            }
        }
        if (lane == 0) g_kcnt[bc] = min(total, MAXDET);
    }
}

// ======== kernel 3: per-image top-100 via histogram selection ========
__global__ void kfinal(const float* __restrict__ boxes,
                       const float* __restrict__ rot,
                       const float* __restrict__ tr,
                       float* __restrict__ out) {
    __shared__ unsigned long long keys[4096];   // 32 KB (also fallback sort buffer)
    __shared__ int hist[NHBIN];                 // 8 KB
    __shared__ unsigned long long coll[256];    // 2 KB
    __shared__ int cnts[NCLS], pref[NCLS + 1];
    __shared__ int psum[256];
    __shared__ int sT, sC, sMn, sMx, sB;

    const int b = blockIdx.x;
    const int tid = threadIdx.x;

    if (tid < NCLS) cnts[tid] = g_kcnt[b * NCLS + tid];
    __syncthreads();
    if (tid == 0) {
        int acc = 0;
        for (int c = 0; c < NCLS; c++) { pref[c] = acc; acc += cnts[c]; }
        pref[NCLS] = acc; sT = acc;
        sMn = 0x7FFFFFFF; sMx = 0; sC = 0; sB = NHBIN;
    }
    __syncthreads();
    const int T = sT;
    const int target = min(T, MAXDET);

    // stage keys: hi<<32 | (c*100+slot)  (order-equivalent to reference flat idx)
    for (int e = tid; e < NCLS * MAXDET; e += blockDim.x) {
        int c = e / MAXDET, s = e - c * MAXDET;
        if (s < cnts[c]) {
            int pos = pref[c] + s;
            unsigned hi = g_khi[(b * NCLS + c) * MAXDET + s];
            keys[pos] = ((unsigned long long)hi << 32) | (unsigned)(c * MAXDET + s);
        }
    }
    for (int e = tid; e < 256; e += blockDim.x) coll[e] = PADKEY;
    for (int e = tid; e < NHBIN; e += blockDim.x) hist[e] = 0;
    __syncthreads();

    if (T > 0) {
        int lmn = 0x7FFFFFFF, lmx = 0;
        for (int e = tid; e < T; e += blockDim.x) {
            int h = (int)(unsigned)(keys[e] >> 32);   // hi < 2^31 always (positive scores)
            lmn = min(lmn, h); lmx = max(lmx, h);
        }
        atomicMin(&sMn, lmn); atomicMax(&sMx, lmx);
        __syncthreads();

        const int mn = sMn;
        const unsigned d = (unsigned)(sMx - mn);
        const int bits = 32 - __clz(d | 1u);
        const int shift = (bits > 11) ? (bits - 11) : 0;

        for (int e = tid; e < T; e += blockDim.x) {
            int bin = (int)(((unsigned)((unsigned)(keys[e] >> 32) - mn)) >> shift);
            atomicAdd(&hist[bin], 1);
        }
        __syncthreads();

        // find cutoff bin B: first bin with cumulative >= target
        {
            const int base = tid * (NHBIN / 256);   // 8 bins per thread
            int s = 0;
            #pragma unroll
            for (int k = 0; k < NHBIN / 256; k++) s += hist[base + k];
            psum[tid] = s;
            for (int off = 1; off < 256; off <<= 1) {
                __syncthreads();
                int v = psum[tid];
                int add = (tid >= off) ? psum[tid - off] : 0;
                __syncthreads();
                psum[tid] = v + add;
            }
            __syncthreads();
            int incl = psum[tid];
            int excl = incl - s;
            if (excl < target && target <= incl) {
                int cum = excl;
                #pragma unroll
                for (int k = 0; k < NHBIN / 256; k++) {
                    cum += hist[base + k];
                    if (cum >= target) { sB = base + k; break; }
                }
            }
            __syncthreads();
        }
        const int B = sB;
        const int mnp = mn;

        for (int e = tid; e < T; e += blockDim.x) {
            int bin = (int)(((unsigned)((unsigned)(keys[e] >> 32) - mnp)) >> shift);
            if (bin <= B) {
                int slot = atomicAdd(&sC, 1);
                if (slot < 256) coll[slot] = keys[e];
            }
        }
        __syncthreads();
    }

    unsigned long long* res;
    if (sC <= 256) {
        bitonic_sort(coll, 256);
        res = coll;
    } else {
        // pathological mass-tie fallback: full sort
        int P = 256; while (P < T) P <<= 1;
        for (int e = tid; e < P; e += blockDim.x)
            if (e >= T) keys[e] = PADKEY;
        __syncthreads();
        bitonic_sort(keys, P);
        res = keys;
    }

    if (tid < MAXDET) {
        int j = tid;
        unsigned long long key = res[j];
        unsigned hi = (unsigned)(key >> 32);
        bool valid = (hi != 0xFFFFFFFFu);
        float s = from_orderable(~hi);
        int packed = (int)(key & 0xFFFFFFFFu);
        int c = valid ? packed / MAXDET : 0;
        int slot = valid ? packed - c * MAXDET : 0;
        int n = valid ? g_kn[(b * NCLS + c) * MAXDET + slot] : 0;

        float* ob = out;
        float* os = out + BATCH * MAXDET * 4;
        float* ol = os  + BATCH * MAXDET;
        float* orr = ol + BATCH * MAXDET;
        float* ot = orr + BATCH * MAXDET * 3;

        const float4 bx = *(const float4*)(boxes + ((long long)b * NPTS + n) * 4);
        int o4 = (b * MAXDET + j) * 4;
        ob[o4 + 0] = valid ? bx.x : -1.f;
        ob[o4 + 1] = valid ? bx.y : -1.f;
        ob[o4 + 2] = valid ? bx.z : -1.f;
        ob[o4 + 3] = valid ? bx.w : -1.f;

        os[b * MAXDET + j] = valid ? s : -1.f;
        ol[b * MAXDET + j] = valid ? (float)c : -1.f;

        long long g3 = ((long long)b * NPTS + n) * 3;
        int o3 = (b * MAXDET + j) * 3;
        #pragma unroll
        for (int k2 = 0; k2 < 3; k2++) {
            orr[o3 + k2] = valid ? rot[g3 + k2] : -1.f;
            ot [o3 + k2] = valid ? tr [g3 + k2] : -1.f;
        }
    }

    // re-zero counters for the next (graph-replayed) invocation
    if (tid < NCLS) g_cnt[b * NCLS + tid] = 0;
}

extern "C" void kernel_launch(void* const* d_in, const int* in_sizes, int n_in,
                              void* d_out, int out_size) {
    const float* boxes = (const float*)d_in[0];
    const float* cls   = (const float*)d_in[1];
    const float* rot   = (const float*)d_in[2];
    const float* tr    = (const float*)d_in[3];
    float* out = (float*)d_out;

    kscan<<<1184, 256>>>((const float4*)cls);
    ksortnms<<<NBC, 256>>>(boxes, cls);
    kfinal<<<BATCH, 256>>>(boxes, rot, tr, out);
}

// round 7
// speedup vs baseline: 2.3834x; 1.0066x over previous
#include <cuda_runtime.h>
#include <cstdint>
#include <cfloat>

#define BATCH 16
#define NPTS  100000
#define NCLS  30
#define TOPK  200
#define MAXDET 100
#define CAP   1024
#define THRESH 0.9955f
#define ELEMS_PER_IMG (NPTS * NCLS)       // 3,000,000
#define TOT4  (BATCH * ELEMS_PER_IMG / 4) // 12,000,000
#define NBC   (BATCH * NCLS)
#define PADKEY 0xFFFFFFFFFFFFFFFFull
#define MASKW 7                            // ceil(200/32)
#define SCAP  2048
#define NHBIN 512
#define USTREAM 8

// -------- device scratch --------
__device__ int      g_cnt [NBC];           // zero-init; re-zeroed by kfinal tail
__device__ float    g_candS[NBC * CAP];
__device__ int      g_candI[NBC * CAP];
__device__ unsigned g_khi[NBC * MAXDET];
__device__ int      g_kn [NBC * MAXDET];
__device__ int      g_kcnt[NBC];

__device__ __forceinline__ unsigned orderable(float f) {
    unsigned u = __float_as_uint(f);
    return u ^ (((int)u >> 31) ? 0xFFFFFFFFu : 0x80000000u);
}
__device__ __forceinline__ float from_orderable(unsigned o) {
    unsigned bits = (o & 0x80000000u) ? (o ^ 0x80000000u) : ~o;
    return __uint_as_float(bits);
}

__device__ __forceinline__ void bitonic_sort(unsigned long long* keys, int P) {
    for (int k = 2; k <= P; k <<= 1) {
        for (int j = k >> 1; j > 0; j >>= 1) {
            for (int i = threadIdx.x; i < P; i += blockDim.x) {
                int ixj = i ^ j;
                if (ixj > i) {
                    bool up = ((i & k) == 0);
                    unsigned long long a = keys[i], b = keys[ixj];
                    if ((a > b) == up) { keys[i] = b; keys[ixj] = a; }
                }
            }
            __syncthreads();
        }
    }
}

// ================= kernel 1: scan, 8 coalesced streams, max4 reduce =================
__global__ void kscan(const float4* __restrict__ cls4) {
    __shared__ int sCnt;
    __shared__ float sVal[SCAP];
    __shared__ int   sIdx[SCAP];

    if (threadIdx.x == 0) sCnt = 0;
    __syncthreads();

    const int S = gridDim.x * blockDim.x;
    const int tid0 = blockIdx.x * blockDim.x + threadIdx.x;

    for (int base = tid0; base < TOT4; base += USTREAM * S) {
        float m[USTREAM];
        #pragma unroll
        for (int k = 0; k < USTREAM; k++) {
            int idx = base + k * S;
            if (idx < TOT4) {
                float4 v = __ldg(&cls4[idx]);
                m[k] = fmaxf(fmaxf(v.x, v.y), fmaxf(v.z, v.w));
            } else m[k] = 0.f;
        }
        #pragma unroll
        for (int k = 0; k < USTREAM; k++) {
            if (m[k] > THRESH) {
                int idx = base + k * S;
                float4 v = __ldg(&cls4[idx]);   // L1 re-load (line resident)
                float vv[4] = {v.x, v.y, v.z, v.w};
                #pragma unroll
                for (int q = 0; q < 4; q++) {
                    if (vv[q] > THRESH) {
                        int slot = atomicAdd(&sCnt, 1);
                        if (slot < SCAP) {
                            sVal[slot] = vv[q];
                            sIdx[slot] = idx * 4 + q;
                        } else {
                            int gidx = idx * 4 + q;
                            int b = gidx / ELEMS_PER_IMG;
                            int off = gidx - b * ELEMS_PER_IMG;
                            int n = off / NCLS;
                            int c = off - n * NCLS;
                            int bc = b * NCLS + c;
                            int gs = atomicAdd(&g_cnt[bc], 1);
                            if (gs < CAP) {
                                g_candS[bc * CAP + gs] = vv[q];
                                g_candI[bc * CAP + gs] = n;
                            }
                        }
                    }
                }
            }
        }
    }
    __syncthreads();

    const int mm = min(sCnt, SCAP);
    for (int e = threadIdx.x; e < mm; e += blockDim.x) {
        int gidx = sIdx[e];
        float v = sVal[e];
        int b = gidx / ELEMS_PER_IMG;
        int off = gidx - b * ELEMS_PER_IMG;
        int n = off / NCLS;
        int c = off - n * NCLS;
        int bc = b * NCLS + c;
        int slot = atomicAdd(&g_cnt[bc], 1);
        if (slot < CAP) {
            g_candS[bc * CAP + slot] = v;
            g_candI[bc * CAP + slot] = n;
        }
    }
}

// ========== kernel 2: exact top-200 + mask NMS (no div) + skip resolve ==========
__global__ void ksortnms(const float* __restrict__ boxes,
                         const float* __restrict__ cls) {
    const int bc = blockIdx.x;
    const int b = bc / NCLS;
    const int c = bc - b * NCLS;
    const int tid = threadIdx.x;

    __shared__ unsigned long long keys[CAP];
    __shared__ float sx1[TOPK], sy1[TOPK], sx2[TOPK], sy2[TOPK], sarea[TOPK], sscore[TOPK];
    __shared__ int sidx[TOPK], slive[TOPK];
    __shared__ unsigned smask[TOPK * MASKW];

    const int cnt = g_cnt[bc];
    const bool normal = (cnt >= TOPK && cnt <= CAP);

    if (normal) {
        int P = 256;
        while (P < cnt) P <<= 1;
        for (int i = tid; i < P; i += blockDim.x) {
            if (i < cnt) {
                unsigned inv = ~orderable(g_candS[bc * CAP + i]);
                keys[i] = ((unsigned long long)inv << 32) | (unsigned)g_candI[bc * CAP + i];
            } else keys[i] = PADKEY;
        }
        __syncthreads();
        bitonic_sort(keys, P);
    } else {
        // exact streaming fallback (unreachable for this data distribution)
        const int HALF = CAP / 2;
        for (int i = tid; i < CAP; i += blockDim.x) keys[i] = PADKEY;
        __syncthreads();
        for (int cs = 0; cs < NPTS; cs += HALF) {
            for (int j = tid; j < HALF; j += blockDim.x) {
                int n = cs + j;
                unsigned long long key = PADKEY;
                if (n < NPTS) {
                    float v = cls[((long long)b * NPTS + n) * NCLS + c];
                    if (v > 0.01f)
                        key = ((unsigned long long)(~orderable(v)) << 32) | (unsigned)n;
                }
                keys[HALF + j] = key;
            }
            __syncthreads();
            bitonic_sort(keys, CAP);
        }
    }

    if (tid < TOPK) {
        int j = tid;
        unsigned long long key = keys[j];
        unsigned hi = (unsigned)(key >> 32);
        bool live = (hi != 0xFFFFFFFFu);
        int n = live ? (int)(key & 0xFFFFFFFFu) : 0;
        sscore[j] = from_orderable(~hi);
        sidx[j] = n;
        const float4 bx = *(const float4*)(boxes + ((long long)b * NPTS + n) * 4);
        sx1[j] = bx.x; sy1[j] = bx.y; sx2[j] = bx.z; sy2[j] = bx.w;
        sarea[j] = fmaxf(bx.z - bx.x, 0.f) * fmaxf(bx.w - bx.y, 0.f);
        slive[j] = live ? 1 : 0;
    }
    __syncthreads();

    // 200 x 224-bit suppression masks; division-free IoU compare
    for (int cell = tid; cell < TOPK * MASKW; cell += blockDim.x) {
        int i = cell / MASKW, w = cell - i * MASKW;
        unsigned m = 0;
        int j0 = w * 32;
        if (j0 + 31 > i) {
            float x1i = sx1[i], y1i = sy1[i], x2i = sx2[i], y2i = sy2[i], ai = sarea[i];
            #pragma unroll 8
            for (int bit = 0; bit < 32; bit++) {
                int j = j0 + bit;
                if (j > i && j < TOPK) {
                    float xx1 = fmaxf(x1i, sx1[j]);
                    float yy1 = fmaxf(y1i, sy1[j]);
                    float xx2 = fminf(x2i, sx2[j]);
                    float yy2 = fminf(y2i, sy2[j]);
                    float inter = fmaxf(xx2 - xx1, 0.f) * fmaxf(yy2 - yy1, 0.f);
                    float uni = ai + sarea[j] - inter;
                    if (inter > 0.5f * fmaxf(uni, 1e-8f)) m |= 1u << bit;
                }
            }
        }
        smask[cell] = m;
    }
    __syncthreads();

    if (tid < 32) {
        const unsigned FULL = 0xFFFFFFFFu;
        int lane = tid;
        unsigned keepw = 0;
        if (lane < MASKW) {
            for (int bit = 0; bit < 32; bit++) {
                int j = lane * 32 + bit;
                if (j < TOPK && slive[j]) keepw |= 1u << bit;
            }
        }
        // skip-list greedy resolve: visit only kept boxes
        unsigned pend = keepw;
        while (true) {
            unsigned cand = pend ? (unsigned)(lane * 32 + __ffs(pend) - 1) : 0x7FFFFFFFu;
            unsigned i = cand;
            #pragma unroll
            for (int off = 16; off; off >>= 1)
                i = min(i, __shfl_xor_sync(FULL, i, off));
            if (i == 0x7FFFFFFFu) break;
            if (lane == (int)(i >> 5)) pend &= ~(1u << (i & 31u));
            unsigned mm = (lane < MASKW) ? smask[i * MASKW + lane] : 0u;
            keepw &= ~mm;
            pend  &= ~mm;
        }
        // order-preserving compaction (first 100 survivors)
        int pc = (lane < MASKW) ? __popc(keepw) : 0;
        int incl = pc;
        #pragma unroll
        for (int off = 1; off < 32; off <<= 1) {
            int v = __shfl_up_sync(FULL, incl, off);
            if (lane >= off) incl += v;
        }
        int excl = incl - pc;
        int total = __shfl_sync(FULL, incl, 31);
        if (lane < MASKW) {
            unsigned wb = keepw;
            int r = excl;
            while (wb) {
                int bit = __ffs(wb) - 1; wb &= wb - 1;
                int j = lane * 32 + bit;
                if (r < MAXDET) {
                    g_khi[bc * MAXDET + r] = ~orderable(sscore[j]);
                    g_kn [bc * MAXDET + r] = sidx[j];
                }
                r++;
            }
        }
        if (lane == 0) g_kcnt[bc] = min(total, MAXDET);
    }
}

// ======== kernel 3: per-image top-100 via 512-bin histogram selection ========
__global__ void kfinal(const float* __restrict__ boxes,
                       const float* __restrict__ rot,
                       const float* __restrict__ tr,
                       float* __restrict__ out) {
    __shared__ unsigned long long keys[4096];
    __shared__ int hist[NHBIN];
    __shared__ unsigned long long coll[256];
    __shared__ int cnts[NCLS], pref[NCLS + 1];
    __shared__ int psum[256];
    __shared__ int sT, sC, sMn, sMx, sB;

    const int b = blockIdx.x;
    const int tid = threadIdx.x;

    if (tid < NCLS) cnts[tid] = g_kcnt[b * NCLS + tid];
    __syncthreads();
    if (tid == 0) {
        int acc = 0;
        for (int c = 0; c < NCLS; c++) { pref[c] = acc; acc += cnts[c]; }
        pref[NCLS] = acc; sT = acc;
        sMn = 0x7FFFFFFF; sMx = 0; sC = 0; sB = NHBIN;
    }
    __syncthreads();
    const int T = sT;
    const int target = min(T, MAXDET);

    for (int e = tid; e < NCLS * MAXDET; e += blockDim.x) {
        int c = e / MAXDET, s = e - c * MAXDET;
        if (s < cnts[c]) {
            int pos = pref[c] + s;
            unsigned hi = g_khi[(b * NCLS + c) * MAXDET + s];
            keys[pos] = ((unsigned long long)hi << 32) | (unsigned)(c * MAXDET + s);
        }
    }
    for (int e = tid; e < 256; e += blockDim.x) coll[e] = PADKEY;
    for (int e = tid; e < NHBIN; e += blockDim.x) hist[e] = 0;
    __syncthreads();

    if (T > 0) {
        int lmn = 0x7FFFFFFF, lmx = 0;
        for (int e = tid; e < T; e += blockDim.x) {
            int h = (int)(unsigned)(keys[e] >> 32);
            lmn = min(lmn, h); lmx = max(lmx, h);
        }
        atomicMin(&sMn, lmn); atomicMax(&sMx, lmx);
        __syncthreads();

        const int mn = sMn;
        const unsigned d = (unsigned)(sMx - mn);
        const int bits = 32 - __clz(d | 1u);
        const int shift = (bits > 9) ? (bits - 9) : 0;

        for (int e = tid; e < T; e += blockDim.x) {
            int bin = (int)(((unsigned)((unsigned)(keys[e] >> 32) - mn)) >> shift);
            atomicAdd(&hist[bin], 1);
        }
        __syncthreads();

        {
            const int base = tid * (NHBIN / 256);   // 2 bins/thread
            int s = 0;
            #pragma unroll
            for (int k = 0; k < NHBIN / 256; k++) s += hist[base + k];
            psum[tid] = s;
            for (int off = 1; off < 256; off <<= 1) {
                __syncthreads();
                int v = psum[tid];
                int add = (tid >= off) ? psum[tid - off] : 0;
                __syncthreads();
                psum[tid] = v + add;
            }
            __syncthreads();
            int incl = psum[tid];
            int excl = incl - s;
            if (excl < target && target <= incl) {
                int cum = excl;
                #pragma unroll
                for (int k = 0; k < NHBIN / 256; k++) {
                    cum += hist[base + k];
                    if (cum >= target) { sB = base + k; break; }
                }
            }
            __syncthreads();
        }
        const int B = sB;

        for (int e = tid; e < T; e += blockDim.x) {
            int bin = (int)(((unsigned)((unsigned)(keys[e] >> 32) - mn)) >> shift);
            if (bin <= B) {
                int slot = atomicAdd(&sC, 1);
                if (slot < 256) coll[slot] = keys[e];
            }
        }
        __syncthreads();
    }

    unsigned long long* res;
    if (sC <= 256) {
        bitonic_sort(coll, 256);
        res = coll;
    } else {
        int P = 256; while (P < T) P <<= 1;
        for (int e = tid; e < P; e += blockDim.x)
            if (e >= T) keys[e] = PADKEY;
        __syncthreads();
        bitonic_sort(keys, P);
        res = keys;
    }

    if (tid < MAXDET) {
        int j = tid;
        unsigned long long key = res[j];
        unsigned hi = (unsigned)(key >> 32);
        bool valid = (hi != 0xFFFFFFFFu);
        float s = from_orderable(~hi);
        int packed = (int)(key & 0xFFFFFFFFu);
        int c = valid ? packed / MAXDET : 0;
        int slot = valid ? packed - c * MAXDET : 0;
        int n = valid ? g_kn[(b * NCLS + c) * MAXDET + slot] : 0;

        float* ob = out;
        float* os = out + BATCH * MAXDET * 4;
        float* ol = os  + BATCH * MAXDET;
        float* orr = ol + BATCH * MAXDET;
        float* ot = orr + BATCH * MAXDET * 3;

        const float4 bx = *(const float4*)(boxes + ((long long)b * NPTS + n) * 4);
        int o4 = (b * MAXDET + j) * 4;
        ob[o4 + 0] = valid ? bx.x : -1.f;
        ob[o4 + 1] = valid ? bx.y : -1.f;
        ob[o4 + 2] = valid ? bx.z : -1.f;
        ob[o4 + 3] = valid ? bx.w : -1.f;

        os[b * MAXDET + j] = valid ? s : -1.f;
        ol[b * MAXDET + j] = valid ? (float)c : -1.f;

        long long g3 = ((long long)b * NPTS + n) * 3;
        int o3 = (b * MAXDET + j) * 3;
        #pragma unroll
        for (int k2 = 0; k2 < 3; k2++) {
            orr[o3 + k2] = valid ? rot[g3 + k2] : -1.f;
            ot [o3 + k2] = valid ? tr [g3 + k2] : -1.f;
        }
    }

    if (tid < NCLS) g_cnt[b * NCLS + tid] = 0;
}

extern "C" void kernel_launch(void* const* d_in, const int* in_sizes, int n_in,
                              void* d_out, int out_size) {
    const float* boxes = (const float*)d_in[0];
    const float* cls   = (const float*)d_in[1];
    const float* rot   = (const float*)d_in[2];
    const float* tr    = (const float*)d_in[3];
    float* out = (float*)d_out;

    kscan<<<1184, 256>>>((const float4*)cls);
    ksortnms<<<NBC, 256>>>(boxes, cls);
    kfinal<<<BATCH, 256>>>(boxes, rot, tr, out);
}